// round 14
// baseline (speedup 1.0000x reference)
#include <cuda_runtime.h>
#include <cuda_fp16.h>
#include <math.h>
#include <stdint.h>

#define DIM   768
#define DFF   3072
#define HEADS 12
#define DK    64
#define MAXTOK 8192

// ---------------- device scratch (no allocation allowed) ----------------
__device__ __half g_act [MAXTOK * DIM];
__device__ __half g_ff  [MAXTOK * DFF];
__device__ __half g_qkvh[MAXTOK * 3 * DIM];
__device__ float  g_x1  [MAXTOK * DIM];
__device__ __half g_wq  [3*DIM * DIM];
__device__ __half g_wp  [DIM   * DIM];
__device__ __half g_w1  [DFF   * DIM];
__device__ __half g_w2  [DIM   * DFF];

// ---------------- helpers ----------------
__device__ __forceinline__ uint32_t smem_u32(const void* p){
    uint32_t a;
    asm("{ .reg .u64 t; cvta.to.shared.u64 t, %1; cvt.u32.u64 %0, t; }":"=r"(a):"l"(p));
    return a;
}
#define SWZ(o) ((o) ^ (((o)>>3)&0x70))

__device__ __forceinline__ void cp16(uint32_t d, const void* s){
    asm volatile("cp.async.cg.shared.global [%0], [%1], 16;"::"r"(d),"l"(s):"memory");
}
__device__ __forceinline__ void cp_commit(){ asm volatile("cp.async.commit_group;":::"memory"); }
template<int N> __device__ __forceinline__ void cp_wait(){
    asm volatile("cp.async.wait_group %0;"::"n"(N):"memory");
}
__device__ __forceinline__ void mma16816(float* d, const uint32_t* a, const uint32_t* b){
    asm volatile(
        "mma.sync.aligned.m16n8k16.row.col.f32.f16.f16.f32 "
        "{%0,%1,%2,%3}, {%4,%5,%6,%7}, {%8,%9}, {%0,%1,%2,%3};\n"
        : "+f"(d[0]), "+f"(d[1]), "+f"(d[2]), "+f"(d[3])
        : "r"(a[0]), "r"(a[1]), "r"(a[2]), "r"(a[3]), "r"(b[0]), "r"(b[1]));
}
__device__ __forceinline__ void ldmx4(uint32_t* r, uint32_t addr){
    asm volatile("ldmatrix.sync.aligned.m8n8.x4.shared.b16 {%0,%1,%2,%3}, [%4];"
        : "=r"(r[0]), "=r"(r[1]), "=r"(r[2]), "=r"(r[3]) : "r"(addr));
}
__device__ __forceinline__ void ldmx4t(uint32_t* r, uint32_t addr){
    asm volatile("ldmatrix.sync.aligned.m8n8.x4.trans.shared.b16 {%0,%1,%2,%3}, [%4];"
        : "=r"(r[0]), "=r"(r[1]), "=r"(r[2]), "=r"(r[3]) : "r"(addr));
}
// packed fp16 2^x
__device__ __forceinline__ uint32_t h2ex2(uint32_t x){
    uint32_t y; asm volatile("ex2.approx.f16x2 %0, %1;" : "=r"(y) : "r"(x)); return y;
}

// ============================================================
// weight repack: all 4 matrices, grid-stride x4 for MLP=4
// ============================================================
#define P1 442368          // 3*DIM*DIM/4
#define P2 589824          // +DIM*DIM/4
#define P3 1179648         // +DFF*DIM/4
#define P4 1769472         // +DIM*DFF/4
#define PT 442368          // P4/4 (threads)

__global__ __launch_bounds__(256) void pack_all(
    const float4* __restrict__ wq, const float4* __restrict__ wp,
    const float4* __restrict__ w1, const float4* __restrict__ w2,
    __half2* __restrict__ oq, __half2* __restrict__ op,
    __half2* __restrict__ o1, __half2* __restrict__ o2)
{
    const int i0 = blockIdx.x * 256 + threadIdx.x;
    if (i0 >= PT) return;
    float4 v[4];
    __half2* dp[4]; int jj[4];
#pragma unroll
    for (int u = 0; u < 4; u++){
        const int i = i0 + u * PT;
        const float4* s; __half2* d; int j;
        if      (i < P1){ s = wq; d = oq; j = i; }
        else if (i < P2){ s = wp; d = op; j = i - P1; }
        else if (i < P3){ s = w1; d = o1; j = i - P2; }
        else            { s = w2; d = o2; j = i - P3; }
        dp[u] = d; jj[u] = j;
        v[u] = s[j];
    }
#pragma unroll
    for (int u = 0; u < 4; u++){
        dp[u][2*jj[u]]   = __floats2half2_rn(v[u].x, v[u].y);
        dp[u][2*jj[u]+1] = __floats2half2_rn(v[u].z, v[u].w);
    }
}

// ============================================================
// LayerNorm -> fp16: one WARP per token (proven round 13)
// ============================================================
__global__ __launch_bounds__(256) void ln_warp(
    const float* __restrict__ x, const float* __restrict__ w,
    const float* __restrict__ b, __half* __restrict__ y)
{
    const int tok  = (blockIdx.x * 256 + threadIdx.x) >> 5;
    const int lane = threadIdx.x & 31;
    const float4* xr = (const float4*)(x + (size_t)tok * DIM);

    float4 v[6];
    float s1 = 0.f, s2 = 0.f;
#pragma unroll
    for (int u = 0; u < 6; u++){
        v[u] = xr[lane + 32 * u];
        s1 += v[u].x + v[u].y + v[u].z + v[u].w;
        s2 += v[u].x*v[u].x + v[u].y*v[u].y + v[u].z*v[u].z + v[u].w*v[u].w;
    }
#pragma unroll
    for (int off = 16; off; off >>= 1){
        s1 += __shfl_xor_sync(0xffffffffu, s1, off);
        s2 += __shfl_xor_sync(0xffffffffu, s2, off);
    }
    const float mu   = s1 * (1.0f / DIM);
    const float rstd = rsqrtf(s2 * (1.0f / DIM) - mu * mu + 1e-5f);

    uint2* yr = (uint2*)(y + (size_t)tok * DIM);
#pragma unroll
    for (int u = 0; u < 6; u++){
        const float4 wv = ((const float4*)w)[lane + 32 * u];
        const float4 bv = ((const float4*)b)[lane + 32 * u];
        const float o0 = (v[u].x - mu) * rstd * wv.x + bv.x;
        const float o1 = (v[u].y - mu) * rstd * wv.y + bv.y;
        const float o2 = (v[u].z - mu) * rstd * wv.z + bv.z;
        const float o3 = (v[u].w - mu) * rstd * wv.w + bv.w;
        const __half2 h0 = __floats2half2_rn(o0, o1);
        const __half2 h1 = __floats2half2_rn(o2, o3);
        uint2 pk;
        pk.x = *(const uint32_t*)&h0;
        pk.y = *(const uint32_t*)&h1;
        yr[lane + 32 * u] = pk;
    }
}

// ============================================================
// hgemm4: 128x128x64 block, 3-STAGE pipeline, ONE barrier/iter.
// Load for tile it+2 targets the stage consumed at it-1; the
// barrier after cp_wait proves all warps finished reading it.
// EPI 1: +bias+res->fp32 | 2: +bias,GELU->fp16 | 3: +bias->fp16
// ============================================================
#define G4_STAGE 32768                 // A 16KB + B 16KB
#define G4_TOTAL (3*G4_STAGE)

template <int EPI>
__global__ __launch_bounds__(256) void hgemm4(
    const __half* __restrict__ A, const __half* __restrict__ B,
    const float* __restrict__ bias, const float* __restrict__ res,
    float* __restrict__ Co, __half* __restrict__ Cp,
    int N, int K)
{
    extern __shared__ char smem[];
    const uint32_t sb = smem_u32(smem);
    const int tid = threadIdx.x;
    const int wid = tid >> 5, lane = tid & 31;
    const int wm = wid & 1;             // m: 2 x 64
    const int wn = wid >> 1;            // n: 4 x 32
    const int r  = lane >> 2;
    const int c2 = (lane & 3) * 2;
    const int bm = blockIdx.y * 128, bn = blockIdx.x * 128;
    const int NIT = K / 64;

    const int j8   = lane >> 3;
    const int arow = (lane & 7) + ((j8 & 1) << 3);
    const int akb  = (j8 >> 1) << 4;
    const int brow = (lane & 7) + ((j8 >> 1) << 3);
    const int bkb  = (j8 & 1) << 4;

    auto load_tile = [&](int it){
        const uint32_t st = sb + (uint32_t)(it % 3) * G4_STAGE;
        const int k0 = it * 64;
        const __half* Ab = A + (size_t)bm * K + k0;
        const __half* Bb = B + (size_t)bn * K + k0;
#pragma unroll
        for (int i = 0; i < 4; i++){
            const int chunk = tid + i * 256;
            const int rr = chunk >> 3, cb = (chunk & 7) * 16;
            const uint32_t so = SWZ((uint32_t)(rr * 128 + cb));
            cp16(st + so,         (const char*)(Ab + (size_t)rr * K) + cb);
            cp16(st + 16384 + so, (const char*)(Bb + (size_t)rr * K) + cb);
        }
        cp_commit();
    };

    float acc[4][4][4] = {};

    load_tile(0);
    load_tile(1);

    for (int it = 0; it < NIT; it++){
        if (it + 2 < NIT){
            cp_wait<1>();          // tile it resident
            __syncthreads();       // all warps done with stage (it-1)%3
            load_tile(it + 2);     // writes stage (it+2)%3 == (it-1)%3
        } else {
            cp_wait<0>();
            __syncthreads();
        }
        const uint32_t sA = sb + (uint32_t)(it % 3) * G4_STAGE;
        const uint32_t sB = sA + 16384;
#pragma unroll
        for (int kc = 0; kc < 4; kc++){
            uint32_t a[4][4];
#pragma unroll
            for (int mt = 0; mt < 4; mt++){
                const uint32_t addr = sA + SWZ((uint32_t)(
                    (wm * 64 + mt * 16 + arow) * 128 + kc * 32 + akb));
                ldmx4(a[mt], addr);
            }
            uint32_t b[4][2];
#pragma unroll
            for (int ntp = 0; ntp < 2; ntp++){
                uint32_t rg[4];
                const uint32_t addr = sB + SWZ((uint32_t)(
                    (wn * 32 + ntp * 16 + brow) * 128 + kc * 32 + bkb));
                ldmx4(rg, addr);
                b[2*ntp][0]   = rg[0]; b[2*ntp][1]   = rg[1];
                b[2*ntp+1][0] = rg[2]; b[2*ntp+1][1] = rg[3];
            }
#pragma unroll
            for (int mt = 0; mt < 4; mt++)
#pragma unroll
                for (int nt = 0; nt < 4; nt++)
                    mma16816(acc[mt][nt], a[mt], b[nt]);
        }
    }

    // ---- epilogue ----
#pragma unroll
    for (int mt = 0; mt < 4; mt++){
#pragma unroll
        for (int nt = 0; nt < 4; nt++){
            const int row0 = bm + wm * 64 + mt * 16 + r;
            const int col  = bn + wn * 32 + nt * 8 + c2;
            const float b0 = bias[col], b1 = bias[col + 1];
            const float* d = acc[mt][nt];
#pragma unroll
            for (int hh = 0; hh < 2; hh++){
                const int rr = row0 + hh * 8;
                float v0 = d[hh * 2 + 0] + b0;
                float v1 = d[hh * 2 + 1] + b1;
                if (EPI == 1) {
                    const float2 rv = *(const float2*)&res[(size_t)rr * N + col];
                    v0 += rv.x; v1 += rv.y;
                    *(float2*)&Co[(size_t)rr * N + col] = make_float2(v0, v1);
                } else if (EPI == 2) {
                    v0 = 0.5f * v0 * (1.0f + erff(v0 * 0.70710678118654752f));
                    v1 = 0.5f * v1 * (1.0f + erff(v1 * 0.70710678118654752f));
                    *(__half2*)&Cp[(size_t)rr * N + col] = __floats2half2_rn(v0, v1);
                } else {
                    *(__half2*)&Cp[(size_t)rr * N + col] = __floats2half2_rn(v0, v1);
                }
            }
        }
    }
}

// ============================================================
// hgemm64: 64x128x64 block tile, 3-stage, one barrier/iter.
// (proj, fc2; EPI = +bias+res->fp32)
// ============================================================
#define G6_STAGE 24576                 // A 8KB + B 16KB
#define G6_TOTAL (3*G6_STAGE)

__global__ __launch_bounds__(256) void hgemm64(
    const __half* __restrict__ A, const __half* __restrict__ B,
    const float* __restrict__ bias, const float* __restrict__ res,
    float* __restrict__ Co, int N, int K)
{
    extern __shared__ char smem[];
    const uint32_t sb = smem_u32(smem);
    const int tid = threadIdx.x;
    const int wid = tid >> 5, lane = tid & 31;
    const int wm = wid & 1;             // m: 2 x 32
    const int wn = wid >> 1;            // n: 4 x 32
    const int r  = lane >> 2;
    const int c2 = (lane & 3) * 2;
    const int bm = blockIdx.y * 64, bn = blockIdx.x * 128;
    const int NIT = K / 64;

    const int j8   = lane >> 3;
    const int arow = (lane & 7) + ((j8 & 1) << 3);
    const int akb  = (j8 >> 1) << 4;
    const int brow = (lane & 7) + ((j8 >> 1) << 3);
    const int bkb  = (j8 & 1) << 4;

    auto load_tile = [&](int it){
        const uint32_t st = sb + (uint32_t)(it % 3) * G6_STAGE;
        const int k0 = it * 64;
        const __half* Ab = A + (size_t)bm * K + k0;
        const __half* Bb = B + (size_t)bn * K + k0;
#pragma unroll
        for (int i = 0; i < 2; i++){
            const int chunk = tid + i * 256;
            const int rr = chunk >> 3, cb = (chunk & 7) * 16;
            cp16(st + SWZ((uint32_t)(rr * 128 + cb)),
                 (const char*)(Ab + (size_t)rr * K) + cb);
        }
#pragma unroll
        for (int i = 0; i < 4; i++){
            const int chunk = tid + i * 256;
            const int rr = chunk >> 3, cb = (chunk & 7) * 16;
            cp16(st + 8192 + SWZ((uint32_t)(rr * 128 + cb)),
                 (const char*)(Bb + (size_t)rr * K) + cb);
        }
        cp_commit();
    };

    float acc[2][4][4] = {};

    load_tile(0);
    load_tile(1);

    for (int it = 0; it < NIT; it++){
        if (it + 2 < NIT){
            cp_wait<1>();
            __syncthreads();
            load_tile(it + 2);
        } else {
            cp_wait<0>();
            __syncthreads();
        }
        const uint32_t sA = sb + (uint32_t)(it % 3) * G6_STAGE;
        const uint32_t sB = sA + 8192;
#pragma unroll
        for (int kc = 0; kc < 4; kc++){
            uint32_t a[2][4];
#pragma unroll
            for (int mt = 0; mt < 2; mt++){
                const uint32_t addr = sA + SWZ((uint32_t)(
                    (wm * 32 + mt * 16 + arow) * 128 + kc * 32 + akb));
                ldmx4(a[mt], addr);
            }
            uint32_t b[4][2];
#pragma unroll
            for (int ntp = 0; ntp < 2; ntp++){
                uint32_t rg[4];
                const uint32_t addr = sB + SWZ((uint32_t)(
                    (wn * 32 + ntp * 16 + brow) * 128 + kc * 32 + bkb));
                ldmx4(rg, addr);
                b[2*ntp][0]   = rg[0]; b[2*ntp][1]   = rg[1];
                b[2*ntp+1][0] = rg[2]; b[2*ntp+1][1] = rg[3];
            }
#pragma unroll
            for (int mt = 0; mt < 2; mt++)
#pragma unroll
                for (int nt = 0; nt < 4; nt++)
                    mma16816(acc[mt][nt], a[mt], b[nt]);
        }
    }

#pragma unroll
    for (int mt = 0; mt < 2; mt++){
#pragma unroll
        for (int nt = 0; nt < 4; nt++){
            const int row0 = bm + wm * 32 + mt * 16 + r;
            const int col  = bn + wn * 32 + nt * 8 + c2;
            const float b0 = bias[col], b1 = bias[col + 1];
            const float* d = acc[mt][nt];
#pragma unroll
            for (int hh = 0; hh < 2; hh++){
                const int rr = row0 + hh * 8;
                const float2 rv = *(const float2*)&res[(size_t)rr * N + col];
                *(float2*)&Co[(size_t)rr * N + col] =
                    make_float2(d[hh*2+0] + b0 + rv.x, d[hh*2+1] + b1 + rv.y);
            }
        }
    }
}

// ============================================================
// flash3: HMMA flash attention, 3-stage KV pipeline (one barrier
// per kv-tile), log2-domain softmax, ldmatrix frags (round 11).
// smem: Q 16K | KV stages 3 x 16K = 64KB total.
// ============================================================
#define FLS 16384                 // one KV stage (K 8K + V 8K)
#define FL_SMEM (16384 + 3*FLS)

__global__ __launch_bounds__(256) void flash3(
    const __half* __restrict__ qkv, __half* __restrict__ outp)
{
    extern __shared__ char smc[];
    const uint32_t sb = smem_u32(smc);
    const uint32_t Qs = sb;

    const int tid = threadIdx.x, w = tid >> 5, lane = tid & 31;
    const int r = lane >> 2, c2 = (lane & 3) * 2;
    const int bh = blockIdx.y;
    const int b = bh / HEADS, h = bh % HEADS;
    const int q0 = blockIdx.x * 128;
    const __half* base = qkv + (size_t)b * 1024 * (3 * DIM) + h * DK;

    const int j8   = lane >> 3;
    const int brow = (lane & 7) + ((j8 >> 1) << 3);
    const int bkb  = (j8 & 1) << 4;
    const uint32_t vrow = (uint32_t)(lane & 15);
    const int jh  = (lane >> 4) & 1;
    const uint32_t vsw = (uint32_t)((lane & 7) << 4);

    // Q tile 128x64 -> swizzled smem (grouped with KV stage 0)
#pragma unroll
    for (int i = 0; i < 4; i++){
        const int chunk = tid + i * 256;
        const int row = chunk >> 3, cb = (chunk & 7) * 16;
        cp16(Qs + SWZ((uint32_t)(row * 128 + cb)),
             (const char*)(base + (size_t)(q0 + row) * (3 * DIM)) + cb);
    }

    auto loadKV = [&](int t){
        const uint32_t sk = sb + 16384 + (uint32_t)(t % 3) * FLS;
        const uint32_t sv = sk + 8192;
        const __half* kb = base + DIM     + (size_t)(t * 64) * (3 * DIM);
        const __half* vb = base + 2 * DIM + (size_t)(t * 64) * (3 * DIM);
#pragma unroll
        for (int i = 0; i < 2; i++){
            const int chunk = tid + i * 256;
            const int row = chunk >> 3, cb = (chunk & 7) * 16;
            const uint32_t so = SWZ((uint32_t)(row * 128 + cb));
            cp16(sk + so, (const char*)(kb + (size_t)row * (3 * DIM)) + cb);
            cp16(sv + so, (const char*)(vb + (size_t)row * (3 * DIM)) + cb);
        }
        cp_commit();
    };

    loadKV(0);          // group 0: Q + KV0
    loadKV(1);          // group 1: KV1

    uint32_t aq[4][4];
    float o[8][4] = {};
    float m0 = -1e30f, m1 = -1e30f, l0 = 0.f, l1 = 0.f;
    const int qrow = w * 16 + r;

    for (int t = 0; t < 16; t++){
        if (t + 2 < 16){
            cp_wait<1>();          // KV tile t (and Q) resident
            __syncthreads();       // all warps done with stage (t-1)%3
            loadKV(t + 2);         // writes stage (t+2)%3 == (t-1)%3
        } else {
            cp_wait<0>();
            __syncthreads();
        }
        if (t == 0){
            const __half2 sc = __half2half2(__float2half(0.18033688f));
            const int arow_q = (lane & 7) + ((j8 & 1) << 3);
            const int akb_q  = (j8 >> 1) << 4;
#pragma unroll
            for (int kc = 0; kc < 4; kc++){
                const uint32_t addr = Qs + SWZ((uint32_t)(
                    (w * 16 + arow_q) * 128 + kc * 32 + akb_q));
                ldmx4(aq[kc], addr);
#pragma unroll
                for (int u = 0; u < 4; u++){
                    __half2 hv = *(__half2*)&aq[kc][u];
                    hv = __hmul2(hv, sc);
                    aq[kc][u] = *(uint32_t*)&hv;
                }
            }
        }
        const uint32_t sK = sb + 16384 + (uint32_t)(t % 3) * FLS;
        const uint32_t sV = sK + 8192;

        // ---- S = Q K^T (log2 domain) ----
        float sf[8][4] = {};
#pragma unroll
        for (int kc = 0; kc < 4; kc++){
            uint32_t bb[8][2];
#pragma unroll
            for (int ntp = 0; ntp < 4; ntp++){
                uint32_t rg[4];
                const uint32_t addr = sK + SWZ((uint32_t)(
                    (ntp * 16 + brow) * 128 + kc * 32 + bkb));
                ldmx4(rg, addr);
                bb[2*ntp][0]   = rg[0]; bb[2*ntp][1]   = rg[1];
                bb[2*ntp+1][0] = rg[2]; bb[2*ntp+1][1] = rg[3];
            }
#pragma unroll
            for (int j = 0; j < 8; j++)
                mma16816(sf[j], aq[kc], bb[j]);
        }

        // ---- online softmax ----
        float mx0 = -1e30f, mx1 = -1e30f;
#pragma unroll
        for (int j = 0; j < 8; j++){
            mx0 = fmaxf(mx0, fmaxf(sf[j][0], sf[j][1]));
            mx1 = fmaxf(mx1, fmaxf(sf[j][2], sf[j][3]));
        }
        mx0 = fmaxf(mx0, __shfl_xor_sync(0xffffffffu, mx0, 1));
        mx0 = fmaxf(mx0, __shfl_xor_sync(0xffffffffu, mx0, 2));
        mx1 = fmaxf(mx1, __shfl_xor_sync(0xffffffffu, mx1, 1));
        mx1 = fmaxf(mx1, __shfl_xor_sync(0xffffffffu, mx1, 2));
        const float mn0 = fmaxf(m0, mx0), mn1 = fmaxf(m1, mx1);
        const float f0 = exp2f(m0 - mn0), f1 = exp2f(m1 - mn1);

        uint32_t pe[8][2];
        float s0 = 0.f, s1 = 0.f;
#pragma unroll
        for (int j = 0; j < 8; j++){
            __half2 a0 = __floats2half2_rn(sf[j][0] - mn0, sf[j][1] - mn0);
            __half2 a1 = __floats2half2_rn(sf[j][2] - mn1, sf[j][3] - mn1);
            pe[j][0] = h2ex2(*(uint32_t*)&a0);
            pe[j][1] = h2ex2(*(uint32_t*)&a1);
            const float2 g0 = __half22float2(*(__half2*)&pe[j][0]);
            const float2 g1 = __half22float2(*(__half2*)&pe[j][1]);
            s0 += g0.x + g0.y;
            s1 += g1.x + g1.y;
        }
        s0 += __shfl_xor_sync(0xffffffffu, s0, 1);
        s0 += __shfl_xor_sync(0xffffffffu, s0, 2);
        s1 += __shfl_xor_sync(0xffffffffu, s1, 1);
        s1 += __shfl_xor_sync(0xffffffffu, s1, 2);
        l0 = l0 * f0 + s0;  l1 = l1 * f1 + s1;
        m0 = mn0;           m1 = mn1;
#pragma unroll
        for (int j = 0; j < 8; j++){
            o[j][0] *= f0; o[j][1] *= f0;
            o[j][2] *= f1; o[j][3] *= f1;
        }

        uint32_t pa[4][4];
#pragma unroll
        for (int kc = 0; kc < 4; kc++){
            pa[kc][0] = pe[2*kc][0];
            pa[kc][1] = pe[2*kc][1];
            pa[kc][2] = pe[2*kc+1][0];
            pa[kc][3] = pe[2*kc+1][1];
        }

        // ---- O += P V ----
#pragma unroll
        for (int kc = 0; kc < 4; kc++){
#pragma unroll
            for (int jp = 0; jp < 4; jp++){
                uint32_t rg[4];
                const int j0 = jp * 2;
                const uint32_t col = (uint32_t)(16 * (j0 + jh));
                const uint32_t addr = sV + (uint32_t)((kc * 16 + vrow) * 128)
                                         + (col ^ vsw);
                ldmx4t(rg, addr);
                mma16816(o[j0],     pa[kc], rg);
                mma16816(o[j0 + 1], pa[kc], rg + 2);
            }
        }
    }

    // ---- epilogue ----
    const float inv0 = 1.0f / l0, inv1 = 1.0f / l1;
    __half* p0 = outp + (size_t)(b * 1024 + q0 + qrow) * DIM + h * DK;
    __half* p1 = p0 + 8 * DIM;
#pragma unroll
    for (int j = 0; j < 8; j++){
        *(__half2*)(p0 + j * 8 + c2) = __floats2half2_rn(o[j][0] * inv0, o[j][1] * inv0);
        *(__half2*)(p1 + j * 8 + c2) = __floats2half2_rn(o[j][2] * inv1, o[j][3] * inv1);
    }
}

// ============================================================
// launch
// ============================================================
extern "C" void kernel_launch(void* const* d_in, const int* in_sizes, int n_in,
                              void* d_out, int out_size)
{
    const float* x      = (const float*)d_in[0];
    const float* ln1_w  = (const float*)d_in[1];
    const float* ln1_b  = (const float*)d_in[2];
    const float* qkv_w  = (const float*)d_in[3];
    const float* qkv_b  = (const float*)d_in[4];
    const float* proj_w = (const float*)d_in[5];
    const float* proj_b = (const float*)d_in[6];
    const float* ln2_w  = (const float*)d_in[7];
    const float* ln2_b  = (const float*)d_in[8];
    const float* fc1_w  = (const float*)d_in[9];
    const float* fc1_b  = (const float*)d_in[10];
    const float* fc2_w  = (const float*)d_in[11];
    const float* fc2_b  = (const float*)d_in[12];
    float* out = (float*)d_out;

    const int M = in_sizes[0] / DIM;   // 8192
    const int B = M / 1024;

    __half *act, *ff, *qkvh, *wq, *wp, *w1, *w2;
    float *x1f;
    cudaGetSymbolAddress((void**)&act,  g_act);
    cudaGetSymbolAddress((void**)&ff,   g_ff);
    cudaGetSymbolAddress((void**)&qkvh, g_qkvh);
    cudaGetSymbolAddress((void**)&x1f,  g_x1);
    cudaGetSymbolAddress((void**)&wq,   g_wq);
    cudaGetSymbolAddress((void**)&wp,   g_wp);
    cudaGetSymbolAddress((void**)&w1,   g_w1);
    cudaGetSymbolAddress((void**)&w2,   g_w2);

    cudaFuncSetAttribute((const void*)flash3,
                         cudaFuncAttributeMaxDynamicSharedMemorySize, FL_SMEM);
    cudaFuncSetAttribute((const void*)hgemm4<2>,
                         cudaFuncAttributeMaxDynamicSharedMemorySize, G4_TOTAL);
    cudaFuncSetAttribute((const void*)hgemm4<3>,
                         cudaFuncAttributeMaxDynamicSharedMemorySize, G4_TOTAL);
    cudaFuncSetAttribute((const void*)hgemm64,
                         cudaFuncAttributeMaxDynamicSharedMemorySize, G6_TOTAL);

    // weight repack, single launch, MLP=4
    pack_all<<<(PT + 255)/256, 256>>>(
        (const float4*)qkv_w, (const float4*)proj_w,
        (const float4*)fc1_w, (const float4*)fc2_w,
        (__half2*)wq, (__half2*)wp, (__half2*)w1, (__half2*)w2);

    // 1) ln1 -> fp16 act
    ln_warp<<<M / 8, 256>>>(x, ln1_w, ln1_b, act);
    // 2) qkv = act @ Wqkv^T + b  (fp16 out)
    hgemm4<3><<<dim3((3*DIM)/128, M/128), 256, G4_TOTAL>>>(
        act, wq, qkv_b, nullptr, nullptr, qkvh, 3*DIM, DIM);
    // 3) attention (HMMA, log2-softmax) -> fp16 act
    flash3<<<dim3(1024/128, B*HEADS), 256, FL_SMEM>>>(qkvh, act);
    // 4) x1 = x + act @ Wproj^T + b  (fp32 out, 64-row tiles)
    hgemm64<<<dim3(DIM/128, M/64), 256, G6_TOTAL>>>(
        act, wp, proj_b, x, x1f, DIM, DIM);
    // 5) ln2 -> fp16 act
    ln_warp<<<M / 8, 256>>>(x1f, ln2_w, ln2_b, act);
    // 6) ff = gelu(act @ Wfc1^T + b)  (fp16 out)
    hgemm4<2><<<dim3(DFF/128, M/128), 256, G4_TOTAL>>>(
        act, w1, fc1_b, nullptr, nullptr, ff, DFF, DIM);
    // 7) out = x1 + ff @ Wfc2^T + b  (fp32 out, 64-row tiles)
    hgemm64<<<dim3(DIM/128, M/64), 256, G6_TOTAL>>>(
        ff, w2, fc2_b, x1f, out, DIM, DFF);
}

// round 15
// speedup vs baseline: 1.0524x; 1.0524x over previous
#include <cuda_runtime.h>
#include <cuda_fp16.h>
#include <math.h>
#include <stdint.h>

#define DIM   768
#define DFF   3072
#define HEADS 12
#define DK    64
#define MAXTOK 8192

// ---------------- device scratch (no allocation allowed) ----------------
__device__ __half g_act [MAXTOK * DIM];
__device__ __half g_ff  [MAXTOK * DFF];
__device__ __half g_qkvh[MAXTOK * 3 * DIM];
__device__ float  g_x1  [MAXTOK * DIM];
__device__ __half g_wq  [3*DIM * DIM];
__device__ __half g_wp  [DIM   * DIM];
__device__ __half g_w1  [DFF   * DIM];
__device__ __half g_w2  [DIM   * DFF];

// ---------------- helpers ----------------
__device__ __forceinline__ uint32_t smem_u32(const void* p){
    uint32_t a;
    asm("{ .reg .u64 t; cvta.to.shared.u64 t, %1; cvt.u32.u64 %0, t; }":"=r"(a):"l"(p));
    return a;
}
#define SWZ(o) ((o) ^ (((o)>>3)&0x70))

__device__ __forceinline__ void cp16(uint32_t d, const void* s){
    asm volatile("cp.async.cg.shared.global [%0], [%1], 16;"::"r"(d),"l"(s):"memory");
}
__device__ __forceinline__ void cp_commit(){ asm volatile("cp.async.commit_group;":::"memory"); }
template<int N> __device__ __forceinline__ void cp_wait(){
    asm volatile("cp.async.wait_group %0;"::"n"(N):"memory");
}
__device__ __forceinline__ void mma16816(float* d, const uint32_t* a, const uint32_t* b){
    asm volatile(
        "mma.sync.aligned.m16n8k16.row.col.f32.f16.f16.f32 "
        "{%0,%1,%2,%3}, {%4,%5,%6,%7}, {%8,%9}, {%0,%1,%2,%3};\n"
        : "+f"(d[0]), "+f"(d[1]), "+f"(d[2]), "+f"(d[3])
        : "r"(a[0]), "r"(a[1]), "r"(a[2]), "r"(a[3]), "r"(b[0]), "r"(b[1]));
}
__device__ __forceinline__ void ldmx4(uint32_t* r, uint32_t addr){
    asm volatile("ldmatrix.sync.aligned.m8n8.x4.shared.b16 {%0,%1,%2,%3}, [%4];"
        : "=r"(r[0]), "=r"(r[1]), "=r"(r[2]), "=r"(r[3]) : "r"(addr));
}
__device__ __forceinline__ void ldmx4t(uint32_t* r, uint32_t addr){
    asm volatile("ldmatrix.sync.aligned.m8n8.x4.trans.shared.b16 {%0,%1,%2,%3}, [%4];"
        : "=r"(r[0]), "=r"(r[1]), "=r"(r[2]), "=r"(r[3]) : "r"(addr));
}
// packed fp16 2^x
__device__ __forceinline__ uint32_t h2ex2(uint32_t x){
    uint32_t y; asm volatile("ex2.approx.f16x2 %0, %1;" : "=r"(y) : "r"(x)); return y;
}

// ============================================================
// weight repack: all 4 matrices, grid-stride x4 for MLP=4
// ============================================================
#define P1 442368          // 3*DIM*DIM/4
#define P2 589824          // +DIM*DIM/4
#define P3 1179648         // +DFF*DIM/4
#define P4 1769472         // +DIM*DFF/4
#define PT 442368          // P4/4 (threads)

__global__ __launch_bounds__(256) void pack_all(
    const float4* __restrict__ wq, const float4* __restrict__ wp,
    const float4* __restrict__ w1, const float4* __restrict__ w2,
    __half2* __restrict__ oq, __half2* __restrict__ op,
    __half2* __restrict__ o1, __half2* __restrict__ o2)
{
    const int i0 = blockIdx.x * 256 + threadIdx.x;
    if (i0 >= PT) return;
    // 4 independent load/store streams per thread (MLP = 4)
    float4 v[4];
    const float4* sp[4]; __half2* dp[4]; int jj[4];
#pragma unroll
    for (int u = 0; u < 4; u++){
        const int i = i0 + u * PT;
        const float4* s; __half2* d; int j;
        if      (i < P1){ s = wq; d = oq; j = i; }
        else if (i < P2){ s = wp; d = op; j = i - P1; }
        else if (i < P3){ s = w1; d = o1; j = i - P2; }
        else            { s = w2; d = o2; j = i - P3; }
        sp[u] = s; dp[u] = d; jj[u] = j;
        v[u] = s[j];
    }
#pragma unroll
    for (int u = 0; u < 4; u++){
        dp[u][2*jj[u]]   = __floats2half2_rn(v[u].x, v[u].y);
        dp[u][2*jj[u]+1] = __floats2half2_rn(v[u].z, v[u].w);
    }
}

// ============================================================
// LayerNorm -> fp16: one WARP per token, pure-shfl reduction,
// 6 strided float4 loads per lane (MLP=6), uint2 stores.
// ============================================================
__global__ __launch_bounds__(256) void ln_warp(
    const float* __restrict__ x, const float* __restrict__ w,
    const float* __restrict__ b, __half* __restrict__ y)
{
    const int tok  = (blockIdx.x * 256 + threadIdx.x) >> 5;
    const int lane = threadIdx.x & 31;
    const float4* xr = (const float4*)(x + (size_t)tok * DIM);

    float4 v[6];
    float s1 = 0.f, s2 = 0.f;
#pragma unroll
    for (int u = 0; u < 6; u++){
        v[u] = xr[lane + 32 * u];
        s1 += v[u].x + v[u].y + v[u].z + v[u].w;
        s2 += v[u].x*v[u].x + v[u].y*v[u].y + v[u].z*v[u].z + v[u].w*v[u].w;
    }
#pragma unroll
    for (int off = 16; off; off >>= 1){
        s1 += __shfl_xor_sync(0xffffffffu, s1, off);
        s2 += __shfl_xor_sync(0xffffffffu, s2, off);
    }
    const float mu   = s1 * (1.0f / DIM);
    const float rstd = rsqrtf(s2 * (1.0f / DIM) - mu * mu + 1e-5f);

    uint2* yr = (uint2*)(y + (size_t)tok * DIM);
#pragma unroll
    for (int u = 0; u < 6; u++){
        const float4 wv = ((const float4*)w)[lane + 32 * u];
        const float4 bv = ((const float4*)b)[lane + 32 * u];
        const float o0 = (v[u].x - mu) * rstd * wv.x + bv.x;
        const float o1 = (v[u].y - mu) * rstd * wv.y + bv.y;
        const float o2 = (v[u].z - mu) * rstd * wv.z + bv.z;
        const float o3 = (v[u].w - mu) * rstd * wv.w + bv.w;
        const __half2 h0 = __floats2half2_rn(o0, o1);
        const __half2 h1 = __floats2half2_rn(o2, o3);
        uint2 pk;
        pk.x = *(const uint32_t*)&h0;
        pk.y = *(const uint32_t*)&h1;
        yr[lane + 32 * u] = pk;
    }
}

// ============================================================
// hgemm4: 128x128x64 block, 8 warps (2m x 4n), warp 64x32.
// f32-accumulate mma, ldmatrix.x4 fragment loads,
// double-buffered cp.async, SW128 smem. (proven rounds 11-13)
// EPI 1: +bias+res->fp32 | 2: +bias,GELU->fp16 | 3: +bias->fp16
// ============================================================
#define G4_STAGE 32768                 // A 16KB + B 16KB
#define G4_TOTAL (2*G4_STAGE)

template <int EPI>
__global__ __launch_bounds__(256) void hgemm4(
    const __half* __restrict__ A, const __half* __restrict__ B,
    const float* __restrict__ bias, const float* __restrict__ res,
    float* __restrict__ Co, __half* __restrict__ Cp,
    int N, int K)
{
    extern __shared__ char smem[];
    const uint32_t sb = smem_u32(smem);
    const int tid = threadIdx.x;
    const int wid = tid >> 5, lane = tid & 31;
    const int wm = wid & 1;             // m: 2 x 64
    const int wn = wid >> 1;            // n: 4 x 32
    const int r  = lane >> 2;
    const int c2 = (lane & 3) * 2;
    const int bm = blockIdx.y * 128, bn = blockIdx.x * 128;
    const int NIT = K / 64;

    const int j8   = lane >> 3;
    const int arow = (lane & 7) + ((j8 & 1) << 3);
    const int akb  = (j8 >> 1) << 4;
    const int brow = (lane & 7) + ((j8 >> 1) << 3);
    const int bkb  = (j8 & 1) << 4;

    auto load_tile = [&](int it){
        const uint32_t st = sb + (uint32_t)(it & 1) * G4_STAGE;
        const int k0 = it * 64;
        const __half* Ab = A + (size_t)bm * K + k0;
        const __half* Bb = B + (size_t)bn * K + k0;
#pragma unroll
        for (int i = 0; i < 4; i++){
            const int chunk = tid + i * 256;
            const int rr = chunk >> 3, cb = (chunk & 7) * 16;
            const uint32_t so = SWZ((uint32_t)(rr * 128 + cb));
            cp16(st + so,         (const char*)(Ab + (size_t)rr * K) + cb);
            cp16(st + 16384 + so, (const char*)(Bb + (size_t)rr * K) + cb);
        }
    };

    float acc[4][4][4] = {};

    load_tile(0); cp_commit();
    load_tile(1); cp_commit();

    for (int it = 0; it < NIT; it++){
        cp_wait<1>();
        __syncthreads();
        const uint32_t sA = sb + (uint32_t)(it & 1) * G4_STAGE;
        const uint32_t sB = sA + 16384;
#pragma unroll
        for (int kc = 0; kc < 4; kc++){
            uint32_t a[4][4];
#pragma unroll
            for (int mt = 0; mt < 4; mt++){
                const uint32_t addr = sA + SWZ((uint32_t)(
                    (wm * 64 + mt * 16 + arow) * 128 + kc * 32 + akb));
                ldmx4(a[mt], addr);
            }
            uint32_t b[4][2];
#pragma unroll
            for (int ntp = 0; ntp < 2; ntp++){
                uint32_t rg[4];
                const uint32_t addr = sB + SWZ((uint32_t)(
                    (wn * 32 + ntp * 16 + brow) * 128 + kc * 32 + bkb));
                ldmx4(rg, addr);
                b[2*ntp][0]   = rg[0]; b[2*ntp][1]   = rg[1];
                b[2*ntp+1][0] = rg[2]; b[2*ntp+1][1] = rg[3];
            }
#pragma unroll
            for (int mt = 0; mt < 4; mt++)
#pragma unroll
                for (int nt = 0; nt < 4; nt++)
                    mma16816(acc[mt][nt], a[mt], b[nt]);
        }
        __syncthreads();
        if (it + 2 < NIT) load_tile(it + 2);
        cp_commit();
    }

    // ---- epilogue ----
#pragma unroll
    for (int mt = 0; mt < 4; mt++){
#pragma unroll
        for (int nt = 0; nt < 4; nt++){
            const int row0 = bm + wm * 64 + mt * 16 + r;
            const int col  = bn + wn * 32 + nt * 8 + c2;
            const float b0 = bias[col], b1 = bias[col + 1];
            const float* d = acc[mt][nt];
#pragma unroll
            for (int hh = 0; hh < 2; hh++){
                const int rr = row0 + hh * 8;
                float v0 = d[hh * 2 + 0] + b0;
                float v1 = d[hh * 2 + 1] + b1;
                if (EPI == 1) {
                    const float2 rv = *(const float2*)&res[(size_t)rr * N + col];
                    v0 += rv.x; v1 += rv.y;
                    *(float2*)&Co[(size_t)rr * N + col] = make_float2(v0, v1);
                } else if (EPI == 2) {
                    v0 = 0.5f * v0 * (1.0f + erff(v0 * 0.70710678118654752f));
                    v1 = 0.5f * v1 * (1.0f + erff(v1 * 0.70710678118654752f));
                    *(__half2*)&Cp[(size_t)rr * N + col] = __floats2half2_rn(v0, v1);
                } else {
                    *(__half2*)&Cp[(size_t)rr * N + col] = __floats2half2_rn(v0, v1);
                }
            }
        }
    }
}

// ============================================================
// hgemm64: 64x128x64 block tile (proven rounds 12-13 — proj, fc2)
// ============================================================
#define G6_STAGE 24576                 // A 8KB + B 16KB
#define G6_TOTAL (2*G6_STAGE)

__global__ __launch_bounds__(256) void hgemm64(
    const __half* __restrict__ A, const __half* __restrict__ B,
    const float* __restrict__ bias, const float* __restrict__ res,
    float* __restrict__ Co, int N, int K)
{
    extern __shared__ char smem[];
    const uint32_t sb = smem_u32(smem);
    const int tid = threadIdx.x;
    const int wid = tid >> 5, lane = tid & 31;
    const int wm = wid & 1;             // m: 2 x 32
    const int wn = wid >> 1;            // n: 4 x 32
    const int r  = lane >> 2;
    const int c2 = (lane & 3) * 2;
    const int bm = blockIdx.y * 64, bn = blockIdx.x * 128;
    const int NIT = K / 64;

    const int j8   = lane >> 3;
    const int arow = (lane & 7) + ((j8 & 1) << 3);
    const int akb  = (j8 >> 1) << 4;
    const int brow = (lane & 7) + ((j8 >> 1) << 3);
    const int bkb  = (j8 & 1) << 4;

    auto load_tile = [&](int it){
        const uint32_t st = sb + (uint32_t)(it & 1) * G6_STAGE;
        const int k0 = it * 64;
        const __half* Ab = A + (size_t)bm * K + k0;
        const __half* Bb = B + (size_t)bn * K + k0;
#pragma unroll
        for (int i = 0; i < 2; i++){
            const int chunk = tid + i * 256;
            const int rr = chunk >> 3, cb = (chunk & 7) * 16;
            cp16(st + SWZ((uint32_t)(rr * 128 + cb)),
                 (const char*)(Ab + (size_t)rr * K) + cb);
        }
#pragma unroll
        for (int i = 0; i < 4; i++){
            const int chunk = tid + i * 256;
            const int rr = chunk >> 3, cb = (chunk & 7) * 16;
            cp16(st + 8192 + SWZ((uint32_t)(rr * 128 + cb)),
                 (const char*)(Bb + (size_t)rr * K) + cb);
        }
    };

    float acc[2][4][4] = {};

    load_tile(0); cp_commit();
    load_tile(1); cp_commit();

    for (int it = 0; it < NIT; it++){
        cp_wait<1>();
        __syncthreads();
        const uint32_t sA = sb + (uint32_t)(it & 1) * G6_STAGE;
        const uint32_t sB = sA + 8192;
#pragma unroll
        for (int kc = 0; kc < 4; kc++){
            uint32_t a[2][4];
#pragma unroll
            for (int mt = 0; mt < 2; mt++){
                const uint32_t addr = sA + SWZ((uint32_t)(
                    (wm * 32 + mt * 16 + arow) * 128 + kc * 32 + akb));
                ldmx4(a[mt], addr);
            }
            uint32_t b[4][2];
#pragma unroll
            for (int ntp = 0; ntp < 2; ntp++){
                uint32_t rg[4];
                const uint32_t addr = sB + SWZ((uint32_t)(
                    (wn * 32 + ntp * 16 + brow) * 128 + kc * 32 + bkb));
                ldmx4(rg, addr);
                b[2*ntp][0]   = rg[0]; b[2*ntp][1]   = rg[1];
                b[2*ntp+1][0] = rg[2]; b[2*ntp+1][1] = rg[3];
            }
#pragma unroll
            for (int mt = 0; mt < 2; mt++)
#pragma unroll
                for (int nt = 0; nt < 4; nt++)
                    mma16816(acc[mt][nt], a[mt], b[nt]);
        }
        __syncthreads();
        if (it + 2 < NIT) load_tile(it + 2);
        cp_commit();
    }

#pragma unroll
    for (int mt = 0; mt < 2; mt++){
#pragma unroll
        for (int nt = 0; nt < 4; nt++){
            const int row0 = bm + wm * 32 + mt * 16 + r;
            const int col  = bn + wn * 32 + nt * 8 + c2;
            const float b0 = bias[col], b1 = bias[col + 1];
            const float* d = acc[mt][nt];
#pragma unroll
            for (int hh = 0; hh < 2; hh++){
                const int rr = row0 + hh * 8;
                const float2 rv = *(const float2*)&res[(size_t)rr * N + col];
                *(float2*)&Co[(size_t)rr * N + col] =
                    make_float2(d[hh*2+0] + b0 + rv.x, d[hh*2+1] + b1 + rv.y);
            }
        }
    }
}

// ============================================================
// flash3: HMMA flash attention (proven rounds 11-13, unchanged)
// ============================================================
#define FL_SMEM 49152

__global__ __launch_bounds__(256) void flash3(
    const __half* __restrict__ qkv, __half* __restrict__ outp)
{
    extern __shared__ char smc[];
    const uint32_t sb = smem_u32(smc);
    const uint32_t Qs  = sb;
    const uint32_t Ks0 = sb + 16384, Ks1 = sb + 24576;
    const uint32_t Vs0 = sb + 32768, Vs1 = sb + 40960;

    const int tid = threadIdx.x, w = tid >> 5, lane = tid & 31;
    const int r = lane >> 2, c2 = (lane & 3) * 2;
    const int bh = blockIdx.y;
    const int b = bh / HEADS, h = bh % HEADS;
    const int q0 = blockIdx.x * 128;
    const __half* base = qkv + (size_t)b * 1024 * (3 * DIM) + h * DK;

    const int j8   = lane >> 3;
    const int brow = (lane & 7) + ((j8 >> 1) << 3);
    const int bkb  = (j8 & 1) << 4;
    const uint32_t vrow = (uint32_t)(lane & 15);
    const int jh  = (lane >> 4) & 1;
    const uint32_t vsw = (uint32_t)((lane & 7) << 4);

#pragma unroll
    for (int i = 0; i < 4; i++){
        const int chunk = tid + i * 256;
        const int row = chunk >> 3, cb = (chunk & 7) * 16;
        cp16(Qs + SWZ((uint32_t)(row * 128 + cb)),
             (const char*)(base + (size_t)(q0 + row) * (3 * DIM)) + cb);
    }

    auto loadKV = [&](int t){
        const uint32_t sk = (t & 1) ? Ks1 : Ks0;
        const uint32_t sv = (t & 1) ? Vs1 : Vs0;
        const __half* kb = base + DIM     + (size_t)(t * 64) * (3 * DIM);
        const __half* vb = base + 2 * DIM + (size_t)(t * 64) * (3 * DIM);
#pragma unroll
        for (int i = 0; i < 2; i++){
            const int chunk = tid + i * 256;
            const int row = chunk >> 3, cb = (chunk & 7) * 16;
            const uint32_t so = SWZ((uint32_t)(row * 128 + cb));
            cp16(sk + so, (const char*)(kb + (size_t)row * (3 * DIM)) + cb);
            cp16(sv + so, (const char*)(vb + (size_t)row * (3 * DIM)) + cb);
        }
    };

    loadKV(0); cp_commit();
    loadKV(1); cp_commit();

    uint32_t aq[4][4];
    float o[8][4] = {};
    float m0 = -1e30f, m1 = -1e30f, l0 = 0.f, l1 = 0.f;
    const int qrow = w * 16 + r;

    for (int t = 0; t < 16; t++){
        cp_wait<1>();
        __syncthreads();
        if (t == 0){
            const __half2 sc = __half2half2(__float2half(0.18033688f));
            const int arow_q = (lane & 7) + ((j8 & 1) << 3);
            const int akb_q  = (j8 >> 1) << 4;
#pragma unroll
            for (int kc = 0; kc < 4; kc++){
                const uint32_t addr = Qs + SWZ((uint32_t)(
                    (w * 16 + arow_q) * 128 + kc * 32 + akb_q));
                ldmx4(aq[kc], addr);
#pragma unroll
                for (int u = 0; u < 4; u++){
                    __half2 hv = *(__half2*)&aq[kc][u];
                    hv = __hmul2(hv, sc);
                    aq[kc][u] = *(uint32_t*)&hv;
                }
            }
        }
        const uint32_t sK = (t & 1) ? Ks1 : Ks0;
        const uint32_t sV = (t & 1) ? Vs1 : Vs0;

        float sf[8][4] = {};
#pragma unroll
        for (int kc = 0; kc < 4; kc++){
            uint32_t bb[8][2];
#pragma unroll
            for (int ntp = 0; ntp < 4; ntp++){
                uint32_t rg[4];
                const uint32_t addr = sK + SWZ((uint32_t)(
                    (ntp * 16 + brow) * 128 + kc * 32 + bkb));
                ldmx4(rg, addr);
                bb[2*ntp][0]   = rg[0]; bb[2*ntp][1]   = rg[1];
                bb[2*ntp+1][0] = rg[2]; bb[2*ntp+1][1] = rg[3];
            }
#pragma unroll
            for (int j = 0; j < 8; j++)
                mma16816(sf[j], aq[kc], bb[j]);
        }

        float mx0 = -1e30f, mx1 = -1e30f;
#pragma unroll
        for (int j = 0; j < 8; j++){
            mx0 = fmaxf(mx0, fmaxf(sf[j][0], sf[j][1]));
            mx1 = fmaxf(mx1, fmaxf(sf[j][2], sf[j][3]));
        }
        mx0 = fmaxf(mx0, __shfl_xor_sync(0xffffffffu, mx0, 1));
        mx0 = fmaxf(mx0, __shfl_xor_sync(0xffffffffu, mx0, 2));
        mx1 = fmaxf(mx1, __shfl_xor_sync(0xffffffffu, mx1, 1));
        mx1 = fmaxf(mx1, __shfl_xor_sync(0xffffffffu, mx1, 2));
        const float mn0 = fmaxf(m0, mx0), mn1 = fmaxf(m1, mx1);
        const float f0 = exp2f(m0 - mn0), f1 = exp2f(m1 - mn1);

        uint32_t pe[8][2];
        float s0 = 0.f, s1 = 0.f;
#pragma unroll
        for (int j = 0; j < 8; j++){
            __half2 a0 = __floats2half2_rn(sf[j][0] - mn0, sf[j][1] - mn0);
            __half2 a1 = __floats2half2_rn(sf[j][2] - mn1, sf[j][3] - mn1);
            pe[j][0] = h2ex2(*(uint32_t*)&a0);
            pe[j][1] = h2ex2(*(uint32_t*)&a1);
            const float2 g0 = __half22float2(*(__half2*)&pe[j][0]);
            const float2 g1 = __half22float2(*(__half2*)&pe[j][1]);
            s0 += g0.x + g0.y;
            s1 += g1.x + g1.y;
        }
        s0 += __shfl_xor_sync(0xffffffffu, s0, 1);
        s0 += __shfl_xor_sync(0xffffffffu, s0, 2);
        s1 += __shfl_xor_sync(0xffffffffu, s1, 1);
        s1 += __shfl_xor_sync(0xffffffffu, s1, 2);
        l0 = l0 * f0 + s0;  l1 = l1 * f1 + s1;
        m0 = mn0;           m1 = mn1;
#pragma unroll
        for (int j = 0; j < 8; j++){
            o[j][0] *= f0; o[j][1] *= f0;
            o[j][2] *= f1; o[j][3] *= f1;
        }

        uint32_t pa[4][4];
#pragma unroll
        for (int kc = 0; kc < 4; kc++){
            pa[kc][0] = pe[2*kc][0];
            pa[kc][1] = pe[2*kc][1];
            pa[kc][2] = pe[2*kc+1][0];
            pa[kc][3] = pe[2*kc+1][1];
        }

#pragma unroll
        for (int kc = 0; kc < 4; kc++){
#pragma unroll
            for (int jp = 0; jp < 4; jp++){
                uint32_t rg[4];
                const int j0 = jp * 2;
                const uint32_t col = (uint32_t)(16 * (j0 + jh));
                const uint32_t addr = sV + (uint32_t)((kc * 16 + vrow) * 128)
                                         + (col ^ vsw);
                ldmx4t(rg, addr);
                mma16816(o[j0],     pa[kc], rg);
                mma16816(o[j0 + 1], pa[kc], rg + 2);
            }
        }

        __syncthreads();
        if (t + 2 < 16) loadKV(t + 2);
        cp_commit();
    }

    const float inv0 = 1.0f / l0, inv1 = 1.0f / l1;
    __half* p0 = outp + (size_t)(b * 1024 + q0 + qrow) * DIM + h * DK;
    __half* p1 = p0 + 8 * DIM;
#pragma unroll
    for (int j = 0; j < 8; j++){
        *(__half2*)(p0 + j * 8 + c2) = __floats2half2_rn(o[j][0] * inv0, o[j][1] * inv0);
        *(__half2*)(p1 + j * 8 + c2) = __floats2half2_rn(o[j][2] * inv1, o[j][3] * inv1);
    }
}

// ============================================================
// launch
// ============================================================
extern "C" void kernel_launch(void* const* d_in, const int* in_sizes, int n_in,
                              void* d_out, int out_size)
{
    const float* x      = (const float*)d_in[0];
    const float* ln1_w  = (const float*)d_in[1];
    const float* ln1_b  = (const float*)d_in[2];
    const float* qkv_w  = (const float*)d_in[3];
    const float* qkv_b  = (const float*)d_in[4];
    const float* proj_w = (const float*)d_in[5];
    const float* proj_b = (const float*)d_in[6];
    const float* ln2_w  = (const float*)d_in[7];
    const float* ln2_b  = (const float*)d_in[8];
    const float* fc1_w  = (const float*)d_in[9];
    const float* fc1_b  = (const float*)d_in[10];
    const float* fc2_w  = (const float*)d_in[11];
    const float* fc2_b  = (const float*)d_in[12];
    float* out = (float*)d_out;

    const int M = in_sizes[0] / DIM;   // 8192
    const int B = M / 1024;

    __half *act, *ff, *qkvh, *wq, *wp, *w1, *w2;
    float *x1f;
    cudaGetSymbolAddress((void**)&act,  g_act);
    cudaGetSymbolAddress((void**)&ff,   g_ff);
    cudaGetSymbolAddress((void**)&qkvh, g_qkvh);
    cudaGetSymbolAddress((void**)&x1f,  g_x1);
    cudaGetSymbolAddress((void**)&wq,   g_wq);
    cudaGetSymbolAddress((void**)&wp,   g_wp);
    cudaGetSymbolAddress((void**)&w1,   g_w1);
    cudaGetSymbolAddress((void**)&w2,   g_w2);

    cudaFuncSetAttribute((const void*)flash3,
                         cudaFuncAttributeMaxDynamicSharedMemorySize, FL_SMEM);
    cudaFuncSetAttribute((const void*)hgemm4<2>,
                         cudaFuncAttributeMaxDynamicSharedMemorySize, G4_TOTAL);
    cudaFuncSetAttribute((const void*)hgemm4<3>,
                         cudaFuncAttributeMaxDynamicSharedMemorySize, G4_TOTAL);
    cudaFuncSetAttribute((const void*)hgemm64,
                         cudaFuncAttributeMaxDynamicSharedMemorySize, G6_TOTAL);

    // weight repack, single launch, MLP=4
    pack_all<<<(PT + 255)/256, 256>>>(
        (const float4*)qkv_w, (const float4*)proj_w,
        (const float4*)fc1_w, (const float4*)fc2_w,
        (__half2*)wq, (__half2*)wp, (__half2*)w1, (__half2*)w2);

    // 1) ln1 -> fp16 act   (warp-per-token: M/8 blocks of 256)
    ln_warp<<<M / 8, 256>>>(x, ln1_w, ln1_b, act);
    // 2) qkv = act @ Wqkv^T + b  (fp16 out)
    hgemm4<3><<<dim3((3*DIM)/128, M/128), 256, G4_TOTAL>>>(
        act, wq, qkv_b, nullptr, nullptr, qkvh, 3*DIM, DIM);
    // 3) attention (HMMA, log2-softmax) -> fp16 act
    flash3<<<dim3(1024/128, B*HEADS), 256, FL_SMEM>>>(qkvh, act);
    // 4) x1 = x + act @ Wproj^T + b  (fp32 out, 64-row tiles)
    hgemm64<<<dim3(DIM/128, M/64), 256, G6_TOTAL>>>(
        act, wp, proj_b, x, x1f, DIM, DIM);
    // 5) ln2 -> fp16 act
    ln_warp<<<M / 8, 256>>>(x1f, ln2_w, ln2_b, act);
    // 6) ff = gelu(act @ Wfc1^T + b)  (fp16 out)
    hgemm4<2><<<dim3(DFF/128, M/128), 256, G4_TOTAL>>>(
        act, w1, fc1_b, nullptr, nullptr, ff, DFF, DIM);
    // 7) out = x1 + ff @ Wfc2^T + b  (fp32 out, 64-row tiles)
    hgemm64<<<dim3(DIM/128, M/64), 256, G6_TOTAL>>>(
        ff, w2, fc2_b, x1f, out, DIM, DFF);
}